// round 15
// baseline (speedup 1.0000x reference)
#include <cuda_runtime.h>
#include <cuda_fp16.h>
#include <math.h>
#include <stdint.h>

#define BB 4
#define SS 2048
#define DD 768
#define HH 12
#define HD 64

#define QSCALE 0.18033688f   // 0.125 * log2(e)

// half scratch
__device__ __half g_xh [BB*SS*DD];
__device__ __half g_wqh[DD*DD];
__device__ __half g_wkh[DD*DD];
__device__ __half g_wvh[DD*DD];
__device__ __half g_woh[DD*DD];
__device__ __half g_q  [BB*HH*SS*HD];   // [bh][s][d] (pre-scaled by QSCALE)
__device__ __half g_k  [BB*HH*SS*HD];   // [bh][s][d]
__device__ __half g_vt [BB*HH*HD*SS];   // [bh][d][s]
__device__ __half g_ctx[BB*SS*DD];      // [b][s][D]

__device__ __forceinline__ void mma16(float* c, uint32_t a0, uint32_t a1,
                                      uint32_t a2, uint32_t a3,
                                      uint32_t b0, uint32_t b1) {
    asm volatile(
        "mma.sync.aligned.m16n8k16.row.col.f32.f16.f16.f32 "
        "{%0,%1,%2,%3}, {%4,%5,%6,%7}, {%8,%9}, {%0,%1,%2,%3};"
        : "+f"(c[0]), "+f"(c[1]), "+f"(c[2]), "+f"(c[3])
        : "r"(a0), "r"(a1), "r"(a2), "r"(a3), "r"(b0), "r"(b1));
}
__device__ __forceinline__ void ldmx4(uint32_t* r, uint32_t addr) {
    asm volatile("ldmatrix.sync.aligned.m8n8.x4.shared.b16 {%0,%1,%2,%3}, [%4];"
        : "=r"(r[0]), "=r"(r[1]), "=r"(r[2]), "=r"(r[3]) : "r"(addr));
}
__device__ __forceinline__ void cpa16(uint32_t s, const void* g) {
    asm volatile("cp.async.cg.shared.global [%0], [%1], 16;" :: "r"(s), "l"(g));
}
__device__ __forceinline__ void cp_commit() { asm volatile("cp.async.commit_group;"); }
__device__ __forceinline__ void cp_wait0()  { asm volatile("cp.async.wait_group 0;"); }

__device__ __forceinline__ uint32_t packh2(float a, float b) {
    __half2 h = __floats2half2_rn(a, b);
    return *(uint32_t*)&h;
}

// ---------------------------------------------------------------------------
__global__ void f2h(const float* __restrict__ src, __half* __restrict__ dst, int n) {
    int i = (blockIdx.x * blockDim.x + threadIdx.x) * 4;
    if (i < n) {
        float4 v = *(const float4*)(src + i);
        *(__half2*)(dst + i)     = __floats2half2_rn(v.x, v.y);
        *(__half2*)(dst + i + 2) = __floats2half2_rn(v.z, v.w);
    }
}

// 4 weight matrices in one launch (each n elements)
__global__ void f2h4(const float* __restrict__ s0, const float* __restrict__ s1,
                     const float* __restrict__ s2, const float* __restrict__ s3,
                     __half* d0, __half* d1, __half* d2, __half* d3, int n)
{
    int i = (blockIdx.x * blockDim.x + threadIdx.x) * 4;
    int sel = i / n, j = i - sel * n;
    const float* s = (sel == 0) ? s0 : (sel == 1) ? s1 : (sel == 2) ? s2 : s3;
    __half* d      = (sel == 0) ? d0 : (sel == 1) ? d1 : (sel == 2) ? d2 : d3;
    float4 v = *(const float4*)(s + j);
    *(__half2*)(d + j)     = __floats2half2_rn(v.x, v.y);
    *(__half2*)(d + j + 2) = __floats2half2_rn(v.z, v.w);
}

// ---------------------------------------------------------------------------
// Shared GEMM mainloop (R11-proven): 128x128 block, BK=32, 2-stage cp.async.
// 8 warps (2m x 4n), warp tile 64x32, fp16 in / f32 accum.
// ---------------------------------------------------------------------------
#define GS 40    // smem row stride (halves)

struct GemmCtx {
    float c[4][4][4];
};

__device__ __forceinline__ void gemm_mainloop(
    const __half* Aposn, const __half* Wposn,
    __half (*As)[128*GS], __half (*Bs)[128*GS],
    int t, int lane, int wm, int wn, GemmCtx& G)
{
    const int lr = t >> 1;
    const int lc = (t & 1) * 16;
    const __half* Ag = Aposn + (size_t)lr * DD + lc;
    const __half* Wg = Wposn + (size_t)lr * DD + lc;

    const uint32_t asb[2] = { (uint32_t)__cvta_generic_to_shared(As[0]),
                              (uint32_t)__cvta_generic_to_shared(As[1]) };
    const uint32_t bsb[2] = { (uint32_t)__cvta_generic_to_shared(Bs[0]),
                              (uint32_t)__cvta_generic_to_shared(Bs[1]) };
    const uint32_t sa = lr * (GS*2) + lc * 2;

    const int a4off = (((lane & 7) + ((lane >> 3) & 1) * 8) * GS + (lane >> 4) * 8) * 2;
    const int b4off = (((lane & 7) + (lane >> 4) * 8) * GS + ((lane >> 3) & 1) * 8) * 2;

    cpa16(asb[0] + sa,      Ag);
    cpa16(asb[0] + sa + 16, Ag + 8);
    cpa16(bsb[0] + sa,      Wg);
    cpa16(bsb[0] + sa + 16, Wg + 8);
    cp_commit();

    const int NIT = DD / 32;   // 24
    for (int it = 0; it < NIT; it++) {
        const int cur = it & 1;
        cp_wait0();
        __syncthreads();
        if (it + 1 < NIT) {
            const int nxt = cur ^ 1;
            const int k0 = (it + 1) * 32;
            cpa16(asb[nxt] + sa,      Ag + k0);
            cpa16(asb[nxt] + sa + 16, Ag + k0 + 8);
            cpa16(bsb[nxt] + sa,      Wg + k0);
            cpa16(bsb[nxt] + sa + 16, Wg + k0 + 8);
            cp_commit();
        }
        #pragma unroll
        for (int ks = 0; ks < 2; ks++) {
            uint32_t a[4][4]; uint32_t b[2][4];
            #pragma unroll
            for (int mt = 0; mt < 4; mt++)
                ldmx4(a[mt], asb[cur] + (wm * 64 + mt * 16) * (GS*2) + a4off + ks * 32);
            #pragma unroll
            for (int np = 0; np < 2; np++)
                ldmx4(b[np], bsb[cur] + (wn * 32 + np * 16) * (GS*2) + b4off + ks * 32);
            #pragma unroll
            for (int mt = 0; mt < 4; mt++)
                #pragma unroll
                for (int np = 0; np < 2; np++) {
                    mma16(G.c[mt][2*np],   a[mt][0], a[mt][1], a[mt][2], a[mt][3],
                          b[np][0], b[np][1]);
                    mma16(G.c[mt][2*np+1], a[mt][0], a[mt][1], a[mt][2], a[mt][3],
                          b[np][2], b[np][3]);
                }
        }
    }
}

// ---------------------------------------------------------------------------
// Fused QKV projection, persistent over m: grid (18, 16); each block does
// 4 m-tiles for one (sel, n0). One wave (288 <= 296 resident).
// ---------------------------------------------------------------------------
__global__ __launch_bounds__(256) void gemm_qkv()
{
    __shared__ __half As[2][128*GS];
    __shared__ __half Bs[2][128*GS];

    const int t = threadIdx.x;
    const int lane = t & 31;
    const int q = lane & 3, g = lane >> 2;
    const int warp = t >> 5;
    const int wm = warp & 1, wn = warp >> 1;
    const int sel = blockIdx.x / 6;
    const int n0 = (blockIdx.x % 6) * 128;

    const __half* W = (sel == 0) ? g_wqh : (sel == 1) ? g_wkh : g_wvh;

    for (int i = 0; i < 4; i++) {
        const int m0 = (blockIdx.y * 4 + i) * 128;

        GemmCtx G = {};
        gemm_mainloop(g_xh + (size_t)m0 * DD, W + (size_t)n0 * DD, As, Bs,
                      t, lane, wm, wn, G);

        #pragma unroll
        for (int mt = 0; mt < 4; mt++) {
            const int r0 = m0 + wm * 64 + mt * 16 + g;
            #pragma unroll
            for (int nt = 0; nt < 4; nt++) {
                const int cc = n0 + wn * 32 + nt * 8 + 2 * q;
                float* cf = G.c[mt][nt];
                const int h = cc >> 6, d = cc & 63;
                const int bi = r0 >> 11, s0 = r0 & (SS - 1), s1 = s0 + 8;
                if (sel == 2) {
                    __half* dst = g_vt + ((size_t)((bi * HH + h) * HD + d)) * SS;
                    dst[s0]      = __float2half(cf[0]);
                    dst[SS + s0] = __float2half(cf[1]);
                    dst[s1]      = __float2half(cf[2]);
                    dst[SS + s1] = __float2half(cf[3]);
                } else {
                    const float sc = (sel == 0) ? QSCALE : 1.0f;
                    __half* dst = (sel == 0) ? g_q : g_k;
                    *(__half2*)(dst + ((size_t)(bi * HH + h) * SS + s0) * HD + d) =
                        __floats2half2_rn(cf[0] * sc, cf[1] * sc);
                    *(__half2*)(dst + ((size_t)(bi * HH + h) * SS + s1) * HD + d) =
                        __floats2half2_rn(cf[2] * sc, cf[3] * sc);
                }
            }
        }
        __syncthreads();   // epilogue smem-free; aligns warps before next prologue
    }
}

// ---------------------------------------------------------------------------
// Out-projection, persistent over m: grid (6, 32); 2 m-tiles per block.
// ---------------------------------------------------------------------------
__global__ __launch_bounds__(256) void gemm_out(
    const float* __restrict__ bias, float* __restrict__ out)
{
    __shared__ __half As[2][128*GS];
    __shared__ __half Bs[2][128*GS];

    const int t = threadIdx.x;
    const int lane = t & 31;
    const int q = lane & 3, g = lane >> 2;
    const int warp = t >> 5;
    const int wm = warp & 1, wn = warp >> 1;
    const int n0 = blockIdx.x * 128;

    for (int i = 0; i < 2; i++) {
        const int m0 = (blockIdx.y * 2 + i) * 128;

        GemmCtx G = {};
        gemm_mainloop(g_ctx + (size_t)m0 * DD, g_woh + (size_t)n0 * DD, As, Bs,
                      t, lane, wm, wn, G);

        #pragma unroll
        for (int mt = 0; mt < 4; mt++) {
            const int r0 = m0 + wm * 64 + mt * 16 + g;
            #pragma unroll
            for (int nt = 0; nt < 4; nt++) {
                const int cc = n0 + wn * 32 + nt * 8 + 2 * q;
                float* cf = G.c[mt][nt];
                float2 bv = *(const float2*)(bias + cc);
                *(float2*)(out + (size_t)r0 * DD + cc) =
                    make_float2(cf[0] + bv.x, cf[1] + bv.y);
                *(float2*)(out + (size_t)(r0 + 8) * DD + cc) =
                    make_float2(cf[2] + bv.x, cf[3] + bv.y);
            }
        }
        __syncthreads();
    }
}

// ---------------------------------------------------------------------------
// FP16 flash attention (exact R11 form), causal, 2-stage cp.async K/V.
// Block = 128 q-rows x 64 kv; warp w owns q-rows 16w..16w+15.
// P stays in registers (S C-fragment repacked as PV A-fragment).
// ---------------------------------------------------------------------------
#define AS 72
#define ATTN_SMEM_BYTES ((4 * 64 * AS + 128 * AS) * 2)   // 55296 B

__global__ __launch_bounds__(256) void attn_h()
{
    extern __shared__ __half smh[];
    __half* Ks0 = smh;
    __half* Ks1 = smh +  64 * AS;
    __half* Vt0 = smh + 128 * AS;
    __half* Vt1 = smh + 192 * AS;
    __half* Ps  = smh + 256 * AS;       // Q staging only

    const int t = threadIdx.x;
    const int lane = t & 31;
    const int q = lane & 3, g = lane >> 2;
    const int w = t >> 5;
    const int qtb = gridDim.x - 1 - blockIdx.x;
    const int bh = blockIdx.y;

    const int krow = t & 63, kuq = t >> 6;
    const int qrow = t & 127, quh = t >> 7;

    const uint32_t ksb[2] = { (uint32_t)__cvta_generic_to_shared(Ks0),
                              (uint32_t)__cvta_generic_to_shared(Ks1) };
    const uint32_t vtb[2] = { (uint32_t)__cvta_generic_to_shared(Vt0),
                              (uint32_t)__cvta_generic_to_shared(Vt1) };
    const uint32_t ps_b = (uint32_t)__cvta_generic_to_shared(Ps);

    const int a4off = (((lane & 7) + ((lane >> 3) & 1) * 8) * AS + (lane >> 4) * 8) * 2;
    const int b4off = (((lane & 7) + (lane >> 4) * 8) * AS + ((lane >> 3) & 1) * 8) * 2;

    const __half* Kg = g_k  + (size_t)bh * SS * HD;
    const __half* Vg = g_vt + (size_t)bh * HD * SS;
    const uint32_t kso = krow * (AS*2) + kuq * 16;
    const int ntiles = 2 * qtb + 2;

    // prologue: tile 0 async; stage Q synchronously
    {
        const __half* kp = Kg + (size_t)krow * HD + kuq * 8;
        const __half* vp = Vg + (size_t)krow * SS + kuq * 8;
        cpa16(ksb[0] + kso,      kp);
        cpa16(ksb[0] + kso + 64, kp + 32);
        cpa16(vtb[0] + kso,      vp);
        cpa16(vtb[0] + kso + 64, vp + 32);
        cp_commit();
    }
    {
        const uint4* Qg = (const uint4*)(g_q + ((size_t)bh * SS + qtb * 128 + qrow) * HD);
        uint4* Pd = (uint4*)&Ps[qrow * AS];
        #pragma unroll
        for (int i = 0; i < 4; i++) {
            int c8 = quh + 2 * i;
            Pd[c8] = Qg[c8];
        }
    }
    __syncthreads();

    uint32_t qa[4][4];
    #pragma unroll
    for (int ks = 0; ks < 4; ks++)
        ldmx4(qa[ks], ps_b + w * 16 * (AS*2) + a4off + ks * 32);

    float o[8][4] = {};
    float m0 = -INFINITY, m1 = -INFINITY, l0 = 0.f, l1 = 0.f;

    const int row0g = 128 * qtb + 16 * w + g;
    const int row1g = row0g + 8;

    for (int kt = 0; kt < ntiles; kt++) {
        const int cur = kt & 1;
        cp_wait0();
        __syncthreads();
        if (kt + 1 < ntiles) {
            const int nxt = cur ^ 1;
            const __half* kp = Kg + (size_t)(64 * (kt + 1) + krow) * HD + kuq * 8;
            const __half* vp = Vg + (size_t)krow * SS + 64 * (kt + 1) + kuq * 8;
            cpa16(ksb[nxt] + kso,      kp);
            cpa16(ksb[nxt] + kso + 64, kp + 32);
            cpa16(vtb[nxt] + kso,      vp);
            cpa16(vtb[nxt] + kso + 64, vp + 32);
            cp_commit();
        }

        if (64 * kt > 128 * qtb + 16 * w + 15) continue;

        // ---- S = Q K^T ----
        float s4[8][4] = {};
        #pragma unroll
        for (int ks = 0; ks < 4; ks++) {
            #pragma unroll
            for (int np = 0; np < 4; np++) {
                uint32_t b[4];
                ldmx4(b, ksb[cur] + np * 16 * (AS*2) + b4off + ks * 32);
                mma16(s4[2*np],   qa[ks][0], qa[ks][1], qa[ks][2], qa[ks][3], b[0], b[1]);
                mma16(s4[2*np+1], qa[ks][0], qa[ks][1], qa[ks][2], qa[ks][3], b[2], b[3]);
            }
        }

        if (64 * kt + 63 > 128 * qtb + 16 * w) {
            #pragma unroll
            for (int nt = 0; nt < 8; nt++) {
                int colg = 64 * kt + 8 * nt + 2 * q;
                if (colg     > row0g) s4[nt][0] = -INFINITY;
                if (colg + 1 > row0g) s4[nt][1] = -INFINITY;
                if (colg     > row1g) s4[nt][2] = -INFINITY;
                if (colg + 1 > row1g) s4[nt][3] = -INFINITY;
            }
        }

        // ---- warp-local online softmax (base-2 domain) ----
        float pm0 = -INFINITY, pm1 = -INFINITY;
        #pragma unroll
        for (int nt = 0; nt < 8; nt++) {
            pm0 = fmaxf(pm0, fmaxf(s4[nt][0], s4[nt][1]));
            pm1 = fmaxf(pm1, fmaxf(s4[nt][2], s4[nt][3]));
        }
        pm0 = fmaxf(pm0, __shfl_xor_sync(0xffffffffu, pm0, 1));
        pm0 = fmaxf(pm0, __shfl_xor_sync(0xffffffffu, pm0, 2));
        pm1 = fmaxf(pm1, __shfl_xor_sync(0xffffffffu, pm1, 1));
        pm1 = fmaxf(pm1, __shfl_xor_sync(0xffffffffu, pm1, 2));

        const float mn0 = fmaxf(m0, pm0), mn1 = fmaxf(m1, pm1);
        const float al0 = exp2f(m0 - mn0), al1 = exp2f(m1 - mn1);
        m0 = mn0; m1 = mn1;

        uint32_t ph[8][2];
        float sum0 = 0.f, sum1 = 0.f;
        #pragma unroll
        for (int nt = 0; nt < 8; nt++) {
            float p0 = exp2f(s4[nt][0] - mn0), p1 = exp2f(s4[nt][1] - mn0);
            float p2 = exp2f(s4[nt][2] - mn1), p3 = exp2f(s4[nt][3] - mn1);
            sum0 += p0 + p1; sum1 += p2 + p3;
            ph[nt][0] = packh2(p0, p1);
            ph[nt][1] = packh2(p2, p3);
        }
        sum0 += __shfl_xor_sync(0xffffffffu, sum0, 1);
        sum0 += __shfl_xor_sync(0xffffffffu, sum0, 2);
        sum1 += __shfl_xor_sync(0xffffffffu, sum1, 1);
        sum1 += __shfl_xor_sync(0xffffffffu, sum1, 2);
        l0 = l0 * al0 + sum0;
        l1 = l1 * al1 + sum1;

        #pragma unroll
        for (int nd = 0; nd < 8; nd++) {
            o[nd][0] *= al0; o[nd][1] *= al0; o[nd][2] *= al1; o[nd][3] *= al1;
        }

        // ---- O += P V (A-fragments direct from registers) ----
        #pragma unroll
        for (int ks = 0; ks < 4; ks++) {
            #pragma unroll
            for (int np = 0; np < 4; np++) {
                uint32_t b[4];
                ldmx4(b, vtb[cur] + np * 16 * (AS*2) + b4off + ks * 32);
                mma16(o[2*np],   ph[2*ks][0], ph[2*ks][1], ph[2*ks+1][0], ph[2*ks+1][1],
                      b[0], b[1]);
                mma16(o[2*np+1], ph[2*ks][0], ph[2*ks][1], ph[2*ks+1][0], ph[2*ks+1][1],
                      b[2], b[3]);
            }
        }
    }

    // ---- epilogue ----
    const float inv0 = 1.0f / l0, inv1 = 1.0f / l1;
    const int b = bh / HH, h = bh % HH;
    const int s0 = 128 * qtb + 16 * w + g, s1 = s0 + 8;
    __half* C0 = g_ctx + ((size_t)b * SS + s0) * DD + h * HD;
    __half* C1 = g_ctx + ((size_t)b * SS + s1) * DD + h * HD;
    #pragma unroll
    for (int nd = 0; nd < 8; nd++) {
        int cc = 8 * nd + 2 * q;
        *(__half2*)(C0 + cc) = __floats2half2_rn(o[nd][0] * inv0, o[nd][1] * inv0);
        *(__half2*)(C1 + cc) = __floats2half2_rn(o[nd][2] * inv1, o[nd][3] * inv1);
    }
}

// ---------------------------------------------------------------------------
extern "C" void kernel_launch(void* const* d_in, const int* in_sizes, int n_in,
                              void* d_out, int out_size)
{
    const float* x  = (const float*)d_in[0];
    const float* wq = (const float*)d_in[1];
    const float* wk = (const float*)d_in[2];
    const float* wv = (const float*)d_in[3];
    const float* wo = (const float*)d_in[4];
    const float* bo = (const float*)d_in[5];
    float* out = (float*)d_out;

    cudaFuncSetAttribute(attn_h,
                         cudaFuncAttributeMaxDynamicSharedMemorySize,
                         ATTN_SMEM_BYTES);

    __half *xh, *wqh, *wkh, *wvh, *woh;
    cudaGetSymbolAddress((void**)&xh,  g_xh);
    cudaGetSymbolAddress((void**)&wqh, g_wqh);
    cudaGetSymbolAddress((void**)&wkh, g_wkh);
    cudaGetSymbolAddress((void**)&wvh, g_wvh);
    cudaGetSymbolAddress((void**)&woh, g_woh);

    const int NX = BB * SS * DD;
    const int NW = DD * DD;
    f2h<<<NX / 1024, 256>>>(x, xh, NX);
    f2h4<<<(4 * NW) / 1024, 256>>>(wq, wk, wv, wo, wqh, wkh, wvh, woh, NW);

    dim3 blk(256);

    gemm_qkv<<<dim3(18, 16), blk>>>();

    attn_h<<<dim3(SS / 128, BB * HH), blk, ATTN_SMEM_BYTES>>>();

    gemm_out<<<dim3(6, 32), blk>>>(bo, out);
}

// round 17
// speedup vs baseline: 1.0920x; 1.0920x over previous
#include <cuda_runtime.h>
#include <cuda_fp16.h>
#include <math.h>
#include <stdint.h>

#define BB 4
#define SS 2048
#define DD 768
#define HH 12
#define HD 64

#define QSCALE 0.18033688f   // 0.125 * log2(e)

// half scratch
__device__ __half g_xh [BB*SS*DD];
__device__ __half g_wqh[DD*DD];
__device__ __half g_wkh[DD*DD];
__device__ __half g_wvh[DD*DD];
__device__ __half g_woh[DD*DD];
__device__ __half g_q  [BB*HH*SS*HD];   // [bh][s][d] (pre-scaled by QSCALE)
__device__ __half g_k  [BB*HH*SS*HD];   // [bh][s][d]
__device__ __half g_vt [BB*HH*HD*SS];   // [bh][d][s]
__device__ __half g_ctx[BB*SS*DD];      // [b][s][D]

__device__ __forceinline__ void mma16(float* c, uint32_t a0, uint32_t a1,
                                      uint32_t a2, uint32_t a3,
                                      uint32_t b0, uint32_t b1) {
    asm volatile(
        "mma.sync.aligned.m16n8k16.row.col.f32.f16.f16.f32 "
        "{%0,%1,%2,%3}, {%4,%5,%6,%7}, {%8,%9}, {%0,%1,%2,%3};"
        : "+f"(c[0]), "+f"(c[1]), "+f"(c[2]), "+f"(c[3])
        : "r"(a0), "r"(a1), "r"(a2), "r"(a3), "r"(b0), "r"(b1));
}
__device__ __forceinline__ void ldmx4(uint32_t* r, uint32_t addr) {
    asm volatile("ldmatrix.sync.aligned.m8n8.x4.shared.b16 {%0,%1,%2,%3}, [%4];"
        : "=r"(r[0]), "=r"(r[1]), "=r"(r[2]), "=r"(r[3]) : "r"(addr));
}
__device__ __forceinline__ void cpa16(uint32_t s, const void* g) {
    asm volatile("cp.async.cg.shared.global [%0], [%1], 16;" :: "r"(s), "l"(g));
}
__device__ __forceinline__ void cp_commit() { asm volatile("cp.async.commit_group;"); }
__device__ __forceinline__ void cp_wait0()  { asm volatile("cp.async.wait_group 0;"); }
__device__ __forceinline__ void cp_wait1()  { asm volatile("cp.async.wait_group 1;"); }

__device__ __forceinline__ uint32_t packh2(float a, float b) {
    __half2 h = __floats2half2_rn(a, b);
    return *(uint32_t*)&h;
}

// ---------------------------------------------------------------------------
__global__ void f2h(const float* __restrict__ src, __half* __restrict__ dst, int n) {
    int i = (blockIdx.x * blockDim.x + threadIdx.x) * 4;
    if (i < n) {
        float4 v = *(const float4*)(src + i);
        *(__half2*)(dst + i)     = __floats2half2_rn(v.x, v.y);
        *(__half2*)(dst + i + 2) = __floats2half2_rn(v.z, v.w);
    }
}

// 4 weight matrices in one launch (each n elements)
__global__ void f2h4(const float* __restrict__ s0, const float* __restrict__ s1,
                     const float* __restrict__ s2, const float* __restrict__ s3,
                     __half* d0, __half* d1, __half* d2, __half* d3, int n)
{
    int i = (blockIdx.x * blockDim.x + threadIdx.x) * 4;
    int sel = i / n, j = i - sel * n;
    const float* s = (sel == 0) ? s0 : (sel == 1) ? s1 : (sel == 2) ? s2 : s3;
    __half* d      = (sel == 0) ? d0 : (sel == 1) ? d1 : (sel == 2) ? d2 : d3;
    float4 v = *(const float4*)(s + j);
    *(__half2*)(d + j)     = __floats2half2_rn(v.x, v.y);
    *(__half2*)(d + j + 2) = __floats2half2_rn(v.z, v.w);
}

// ---------------------------------------------------------------------------
// Shared GEMM mainloop (R11-proven, best measured): 128x128 block, BK=32,
// 2-stage cp.async. 8 warps (2m x 4n), warp tile 64x32, fp16 in / f32 accum.
// ---------------------------------------------------------------------------
#define GS 40    // smem row stride (halves)

struct GemmCtx {
    float c[4][4][4];
};

__device__ __forceinline__ void gemm_mainloop(
    const __half* Aposn, const __half* Wposn,
    __half (*As)[128*GS], __half (*Bs)[128*GS],
    int t, int lane, int wm, int wn, GemmCtx& G)
{
    const int lr = t >> 1;
    const int lc = (t & 1) * 16;
    const __half* Ag = Aposn + (size_t)lr * DD + lc;
    const __half* Wg = Wposn + (size_t)lr * DD + lc;

    const uint32_t asb[2] = { (uint32_t)__cvta_generic_to_shared(As[0]),
                              (uint32_t)__cvta_generic_to_shared(As[1]) };
    const uint32_t bsb[2] = { (uint32_t)__cvta_generic_to_shared(Bs[0]),
                              (uint32_t)__cvta_generic_to_shared(Bs[1]) };
    const uint32_t sa = lr * (GS*2) + lc * 2;

    const int a4off = (((lane & 7) + ((lane >> 3) & 1) * 8) * GS + (lane >> 4) * 8) * 2;
    const int b4off = (((lane & 7) + (lane >> 4) * 8) * GS + ((lane >> 3) & 1) * 8) * 2;

    cpa16(asb[0] + sa,      Ag);
    cpa16(asb[0] + sa + 16, Ag + 8);
    cpa16(bsb[0] + sa,      Wg);
    cpa16(bsb[0] + sa + 16, Wg + 8);
    cp_commit();

    const int NIT = DD / 32;   // 24
    for (int it = 0; it < NIT; it++) {
        const int cur = it & 1;
        cp_wait0();
        __syncthreads();
        if (it + 1 < NIT) {
            const int nxt = cur ^ 1;
            const int k0 = (it + 1) * 32;
            cpa16(asb[nxt] + sa,      Ag + k0);
            cpa16(asb[nxt] + sa + 16, Ag + k0 + 8);
            cpa16(bsb[nxt] + sa,      Wg + k0);
            cpa16(bsb[nxt] + sa + 16, Wg + k0 + 8);
            cp_commit();
        }
        #pragma unroll
        for (int ks = 0; ks < 2; ks++) {
            uint32_t a[4][4]; uint32_t b[2][4];
            #pragma unroll
            for (int mt = 0; mt < 4; mt++)
                ldmx4(a[mt], asb[cur] + (wm * 64 + mt * 16) * (GS*2) + a4off + ks * 32);
            #pragma unroll
            for (int np = 0; np < 2; np++)
                ldmx4(b[np], bsb[cur] + (wn * 32 + np * 16) * (GS*2) + b4off + ks * 32);
            #pragma unroll
            for (int mt = 0; mt < 4; mt++)
                #pragma unroll
                for (int np = 0; np < 2; np++) {
                    mma16(G.c[mt][2*np],   a[mt][0], a[mt][1], a[mt][2], a[mt][3],
                          b[np][0], b[np][1]);
                    mma16(G.c[mt][2*np+1], a[mt][0], a[mt][1], a[mt][2], a[mt][3],
                          b[np][2], b[np][3]);
                }
        }
    }
}

// ---------------------------------------------------------------------------
// Fused QKV projection: grid (18, 64). sel = bx/6 chooses Q/K/V.
// ---------------------------------------------------------------------------
__global__ __launch_bounds__(256) void gemm_qkv()
{
    __shared__ __half As[2][128*GS];
    __shared__ __half Bs[2][128*GS];

    const int t = threadIdx.x;
    const int lane = t & 31;
    const int q = lane & 3, g = lane >> 2;
    const int warp = t >> 5;
    const int wm = warp & 1, wn = warp >> 1;
    const int sel = blockIdx.x / 6;
    const int n0 = (blockIdx.x % 6) * 128;
    const int m0 = blockIdx.y * 128;

    const __half* W = (sel == 0) ? g_wqh : (sel == 1) ? g_wkh : g_wvh;

    GemmCtx G = {};
    gemm_mainloop(g_xh + (size_t)m0 * DD, W + (size_t)n0 * DD, As, Bs,
                  t, lane, wm, wn, G);

    #pragma unroll
    for (int mt = 0; mt < 4; mt++) {
        const int r0 = m0 + wm * 64 + mt * 16 + g;
        #pragma unroll
        for (int nt = 0; nt < 4; nt++) {
            const int cc = n0 + wn * 32 + nt * 8 + 2 * q;
            float* cf = G.c[mt][nt];
            const int h = cc >> 6, d = cc & 63;
            const int bi = r0 >> 11, s0 = r0 & (SS - 1), s1 = s0 + 8;
            if (sel == 2) {
                __half* dst = g_vt + ((size_t)((bi * HH + h) * HD + d)) * SS;
                dst[s0]      = __float2half(cf[0]);
                dst[SS + s0] = __float2half(cf[1]);
                dst[s1]      = __float2half(cf[2]);
                dst[SS + s1] = __float2half(cf[3]);
            } else {
                const float sc = (sel == 0) ? QSCALE : 1.0f;
                __half* dst = (sel == 0) ? g_q : g_k;
                *(__half2*)(dst + ((size_t)(bi * HH + h) * SS + s0) * HD + d) =
                    __floats2half2_rn(cf[0] * sc, cf[1] * sc);
                *(__half2*)(dst + ((size_t)(bi * HH + h) * SS + s1) * HD + d) =
                    __floats2half2_rn(cf[2] * sc, cf[3] * sc);
            }
        }
    }
}

// ---------------------------------------------------------------------------
// Out-projection: C = ctx @ wo^T + bias -> f32 out.  Grid (6, 64).
// ---------------------------------------------------------------------------
__global__ __launch_bounds__(256) void gemm_out(
    const float* __restrict__ bias, float* __restrict__ out)
{
    __shared__ __half As[2][128*GS];
    __shared__ __half Bs[2][128*GS];

    const int t = threadIdx.x;
    const int lane = t & 31;
    const int q = lane & 3, g = lane >> 2;
    const int warp = t >> 5;
    const int wm = warp & 1, wn = warp >> 1;
    const int m0 = blockIdx.y * 128, n0 = blockIdx.x * 128;

    GemmCtx G = {};
    gemm_mainloop(g_ctx + (size_t)m0 * DD, g_woh + (size_t)n0 * DD, As, Bs,
                  t, lane, wm, wn, G);

    #pragma unroll
    for (int mt = 0; mt < 4; mt++) {
        const int r0 = m0 + wm * 64 + mt * 16 + g;
        #pragma unroll
        for (int nt = 0; nt < 4; nt++) {
            const int cc = n0 + wn * 32 + nt * 8 + 2 * q;
            float* cf = G.c[mt][nt];
            float2 bv = *(const float2*)(bias + cc);
            *(float2*)(out + (size_t)r0 * DD + cc) =
                make_float2(cf[0] + bv.x, cf[1] + bv.y);
            *(float2*)(out + (size_t)(r0 + 8) * DD + cc) =
                make_float2(cf[2] + bv.x, cf[3] + bv.y);
        }
    }
}

// ---------------------------------------------------------------------------
// FP16 flash attention (R13-proven 3-stage form), causal.
// Block = 128 q-rows x 64 kv; warp w owns q-rows 16w..16w+15.
// P stays in registers (S C-fragment repacked as PV A-fragment).
// ---------------------------------------------------------------------------
#define AS 72
#define ASTAGE (64 * AS)                           // halves per K (or V) stage
#define ATTN_SMEM_BYTES ((6 * ASTAGE + 128 * AS) * 2)   // 73728 B

__global__ __launch_bounds__(256) void attn_h()
{
    extern __shared__ __half smh[];
    __half* Ksb = smh;                   // 3 stages
    __half* Vtb = smh + 3 * ASTAGE;      // 3 stages
    __half* Ps  = smh + 6 * ASTAGE;      // Q staging only

    const int t = threadIdx.x;
    const int lane = t & 31;
    const int q = lane & 3, g = lane >> 2;
    const int w = t >> 5;
    const int qtb = gridDim.x - 1 - blockIdx.x;
    const int bh = blockIdx.y;

    const int krow = t & 63, kuq = t >> 6;
    const int qrow = t & 127, quh = t >> 7;

    const uint32_t ks0 = (uint32_t)__cvta_generic_to_shared(Ksb);
    const uint32_t vt0 = (uint32_t)__cvta_generic_to_shared(Vtb);
    const uint32_t ps_b = (uint32_t)__cvta_generic_to_shared(Ps);

    const int a4off = (((lane & 7) + ((lane >> 3) & 1) * 8) * AS + (lane >> 4) * 8) * 2;
    const int b4off = (((lane & 7) + (lane >> 4) * 8) * AS + ((lane >> 3) & 1) * 8) * 2;

    const __half* Kg = g_k  + (size_t)bh * SS * HD;
    const __half* Vg = g_vt + (size_t)bh * HD * SS;
    const uint32_t kso = krow * (AS*2) + kuq * 16;
    const int ntiles = 2 * qtb + 2;   // >= 2 always

    // prologue: tiles 0 and 1 async; stage Q synchronously
    #pragma unroll
    for (int p = 0; p < 2; p++) {
        const __half* kp = Kg + (size_t)(64 * p + krow) * HD + kuq * 8;
        const __half* vp = Vg + (size_t)krow * SS + 64 * p + kuq * 8;
        const uint32_t kb = ks0 + p * (ASTAGE*2), vb = vt0 + p * (ASTAGE*2);
        cpa16(kb + kso,      kp);
        cpa16(kb + kso + 64, kp + 32);
        cpa16(vb + kso,      vp);
        cpa16(vb + kso + 64, vp + 32);
        cp_commit();
    }
    {
        const uint4* Qg = (const uint4*)(g_q + ((size_t)bh * SS + qtb * 128 + qrow) * HD);
        uint4* Pd = (uint4*)&Ps[qrow * AS];
        #pragma unroll
        for (int i = 0; i < 4; i++) {
            int c8 = quh + 2 * i;
            Pd[c8] = Qg[c8];
        }
    }
    __syncthreads();

    uint32_t qa[4][4];
    #pragma unroll
    for (int ks = 0; ks < 4; ks++)
        ldmx4(qa[ks], ps_b + w * 16 * (AS*2) + a4off + ks * 32);

    float o[8][4] = {};
    float m0 = -INFINITY, m1 = -INFINITY, l0 = 0.f, l1 = 0.f;

    const int row0g = 128 * qtb + 16 * w + g;
    const int row1g = row0g + 8;

    int cur = 0;
    for (int kt = 0; kt < ntiles; kt++) {
        cp_wait1();          // tile kt resident
        __syncthreads();
        if (kt + 2 < ntiles) {
            int nxt = cur + 2; if (nxt >= 3) nxt -= 3;
            const __half* kp = Kg + (size_t)(64 * (kt + 2) + krow) * HD + kuq * 8;
            const __half* vp = Vg + (size_t)krow * SS + 64 * (kt + 2) + kuq * 8;
            const uint32_t kb = ks0 + nxt * (ASTAGE*2), vb = vt0 + nxt * (ASTAGE*2);
            cpa16(kb + kso,      kp);
            cpa16(kb + kso + 64, kp + 32);
            cpa16(vb + kso,      vp);
            cpa16(vb + kso + 64, vp + 32);
            cp_commit();
        }
        const uint32_t kcur = ks0 + cur * (ASTAGE*2);
        const uint32_t vcur = vt0 + cur * (ASTAGE*2);
        if (++cur == 3) cur = 0;

        if (64 * kt > 128 * qtb + 16 * w + 15) continue;

        // ---- S = Q K^T ----
        float s4[8][4] = {};
        #pragma unroll
        for (int ks = 0; ks < 4; ks++) {
            #pragma unroll
            for (int np = 0; np < 4; np++) {
                uint32_t b[4];
                ldmx4(b, kcur + np * 16 * (AS*2) + b4off + ks * 32);
                mma16(s4[2*np],   qa[ks][0], qa[ks][1], qa[ks][2], qa[ks][3], b[0], b[1]);
                mma16(s4[2*np+1], qa[ks][0], qa[ks][1], qa[ks][2], qa[ks][3], b[2], b[3]);
            }
        }

        if (64 * kt + 63 > 128 * qtb + 16 * w) {
            #pragma unroll
            for (int nt = 0; nt < 8; nt++) {
                int colg = 64 * kt + 8 * nt + 2 * q;
                if (colg     > row0g) s4[nt][0] = -INFINITY;
                if (colg + 1 > row0g) s4[nt][1] = -INFINITY;
                if (colg     > row1g) s4[nt][2] = -INFINITY;
                if (colg + 1 > row1g) s4[nt][3] = -INFINITY;
            }
        }

        // ---- warp-local online softmax (base-2 domain) ----
        float pm0 = -INFINITY, pm1 = -INFINITY;
        #pragma unroll
        for (int nt = 0; nt < 8; nt++) {
            pm0 = fmaxf(pm0, fmaxf(s4[nt][0], s4[nt][1]));
            pm1 = fmaxf(pm1, fmaxf(s4[nt][2], s4[nt][3]));
        }
        pm0 = fmaxf(pm0, __shfl_xor_sync(0xffffffffu, pm0, 1));
        pm0 = fmaxf(pm0, __shfl_xor_sync(0xffffffffu, pm0, 2));
        pm1 = fmaxf(pm1, __shfl_xor_sync(0xffffffffu, pm1, 1));
        pm1 = fmaxf(pm1, __shfl_xor_sync(0xffffffffu, pm1, 2));

        const float mn0 = fmaxf(m0, pm0), mn1 = fmaxf(m1, pm1);
        const float al0 = exp2f(m0 - mn0), al1 = exp2f(m1 - mn1);
        m0 = mn0; m1 = mn1;

        uint32_t ph[8][2];
        float sum0 = 0.f, sum1 = 0.f;
        #pragma unroll
        for (int nt = 0; nt < 8; nt++) {
            float p0 = exp2f(s4[nt][0] - mn0), p1 = exp2f(s4[nt][1] - mn0);
            float p2 = exp2f(s4[nt][2] - mn1), p3 = exp2f(s4[nt][3] - mn1);
            sum0 += p0 + p1; sum1 += p2 + p3;
            ph[nt][0] = packh2(p0, p1);
            ph[nt][1] = packh2(p2, p3);
        }
        sum0 += __shfl_xor_sync(0xffffffffu, sum0, 1);
        sum0 += __shfl_xor_sync(0xffffffffu, sum0, 2);
        sum1 += __shfl_xor_sync(0xffffffffu, sum1, 1);
        sum1 += __shfl_xor_sync(0xffffffffu, sum1, 2);
        l0 = l0 * al0 + sum0;
        l1 = l1 * al1 + sum1;

        #pragma unroll
        for (int nd = 0; nd < 8; nd++) {
            o[nd][0] *= al0; o[nd][1] *= al0; o[nd][2] *= al1; o[nd][3] *= al1;
        }

        // ---- O += P V ----
        #pragma unroll
        for (int ks = 0; ks < 4; ks++) {
            #pragma unroll
            for (int np = 0; np < 4; np++) {
                uint32_t b[4];
                ldmx4(b, vcur + np * 16 * (AS*2) + b4off + ks * 32);
                mma16(o[2*np],   ph[2*ks][0], ph[2*ks][1], ph[2*ks+1][0], ph[2*ks+1][1],
                      b[0], b[1]);
                mma16(o[2*np+1], ph[2*ks][0], ph[2*ks][1], ph[2*ks+1][0], ph[2*ks+1][1],
                      b[2], b[3]);
            }
        }
    }

    // ---- epilogue ----
    const float inv0 = 1.0f / l0, inv1 = 1.0f / l1;
    const int b = bh / HH, h = bh % HH;
    const int s0 = 128 * qtb + 16 * w + g, s1 = s0 + 8;
    __half* C0 = g_ctx + ((size_t)b * SS + s0) * DD + h * HD;
    __half* C1 = g_ctx + ((size_t)b * SS + s1) * DD + h * HD;
    #pragma unroll
    for (int nd = 0; nd < 8; nd++) {
        int cc = 8 * nd + 2 * q;
        *(__half2*)(C0 + cc) = __floats2half2_rn(o[nd][0] * inv0, o[nd][1] * inv0);
        *(__half2*)(C1 + cc) = __floats2half2_rn(o[nd][2] * inv1, o[nd][3] * inv1);
    }
}

// ---------------------------------------------------------------------------
extern "C" void kernel_launch(void* const* d_in, const int* in_sizes, int n_in,
                              void* d_out, int out_size)
{
    const float* x  = (const float*)d_in[0];
    const float* wq = (const float*)d_in[1];
    const float* wk = (const float*)d_in[2];
    const float* wv = (const float*)d_in[3];
    const float* wo = (const float*)d_in[4];
    const float* bo = (const float*)d_in[5];
    float* out = (float*)d_out;

    cudaFuncSetAttribute(attn_h,
                         cudaFuncAttributeMaxDynamicSharedMemorySize,
                         ATTN_SMEM_BYTES);

    __half *xh, *wqh, *wkh, *wvh, *woh;
    cudaGetSymbolAddress((void**)&xh,  g_xh);
    cudaGetSymbolAddress((void**)&wqh, g_wqh);
    cudaGetSymbolAddress((void**)&wkh, g_wkh);
    cudaGetSymbolAddress((void**)&wvh, g_wvh);
    cudaGetSymbolAddress((void**)&woh, g_woh);

    const int NX = BB * SS * DD;
    const int NW = DD * DD;
    f2h<<<NX / 1024, 256>>>(x, xh, NX);
    f2h4<<<(4 * NW) / 1024, 256>>>(wq, wk, wv, wo, wqh, wkh, wvh, woh, NW);

    dim3 blk(256);

    gemm_qkv<<<dim3(18, 64), blk>>>();

    attn_h<<<dim3(SS / 128, BB * HH), blk, ATTN_SMEM_BYTES>>>();

    gemm_out<<<dim3(6, 64), blk>>>(bo, out);
}